// round 8
// baseline (speedup 1.0000x reference)
#include <cuda_runtime.h>
#include <math.h>
#include <stdint.h>

#define N_NODES 200000
#define E_EDGES 800000
#define NBATCH  16
#define PK      208   // 193 padded to multiple of 16

// ---------------- scratch (static; no cudaMalloc) ----------------
__device__ __align__(16) float    g_x   [(size_t)N_NODES * 128];
__device__ __align__(16) float    g_aggA[(size_t)N_NODES * 64];
__device__ __align__(16) float    g_aggB[(size_t)N_NODES * 64];
__device__ __align__(16) float    g_y   [(size_t)N_NODES * 64];
__device__ __align__(16) float    g_rn  [N_NODES];
__device__ __align__(16) float    g_deg [N_NODES];
__device__ __align__(16) float    g_wpad[PK * 128];
__device__ __align__(16) unsigned g_gmax[NBATCH * 64];
__device__ __align__(16) float    g_gsum[NBATCH * 64];
__device__ __align__(16) float    g_cnt [NBATCH];

// ---------------- helpers ----------------
__device__ __forceinline__ unsigned fenc(float f) {
    unsigned u = __float_as_uint(f);
    return (u & 0x80000000u) ? ~u : (u | 0x80000000u);
}
__device__ __forceinline__ float fdec(unsigned u) {
    return (u & 0x80000000u) ? __uint_as_float(u & 0x7FFFFFFFu) : __uint_as_float(~u);
}

__global__ void zero_f(float* p, size_t n) {
    size_t i = (size_t)blockIdx.x * blockDim.x + threadIdx.x;
    if (i < n) p[i] = 0.f;
}

__global__ void pool_init_kernel() {
    int i = blockIdx.x * blockDim.x + threadIdx.x;
    if (i < NBATCH * 64) { g_gmax[i] = 0u; g_gsum[i] = 0.f; }
    if (i < NBATCH) g_cnt[i] = 0.f;
}

__global__ void pad_w_kernel(const float* __restrict__ lin_w) {
    int t = blockIdx.x * blockDim.x + threadIdx.x;
    if (t >= PK * 128) return;
    int k = t / 128, j = t % 128;
    g_wpad[t] = (k < 193) ? lin_w[k * 128 + j] : 0.f;
}

__global__ void deg_kernel(const int* __restrict__ dst) {
    int e = blockIdx.x * blockDim.x + threadIdx.x;
    if (e < E_EDGES) atomicAdd(&g_deg[dst[e]], 1.f);
}
__global__ void deginv_kernel() {
    int n = blockIdx.x * blockDim.x + threadIdx.x;
    if (n < N_NODES) g_deg[n] = 1.f / fmaxf(g_deg[n], 1.f);
}

// ---------------- tf32 split helpers ----------------
__device__ __forceinline__ uint2 split2(float x) {
    uint32_t hb;
    asm("cvt.rna.tf32.f32 %0, %1;" : "=r"(hb) : "f"(x));
    return make_uint2(hb, __float_as_uint(x - __uint_as_float(hb)));
}

__device__ __forceinline__ void mma8(float* c, const uint32_t* a, const uint32_t* b) {
    asm("mma.sync.aligned.m16n8k8.row.col.f32.tf32.tf32.f32 "
        "{%0,%1,%2,%3}, {%4,%5,%6,%7}, {%8,%9}, {%0,%1,%2,%3};"
        : "+f"(c[0]), "+f"(c[1]), "+f"(c[2]), "+f"(c[3])
        : "r"(a[0]), "r"(a[1]), "r"(a[2]), "r"(a[3]), "r"(b[0]), "r"(b[1]));
}

// swizzled indices into uint2 arrays
__device__ __forceinline__ int idxA(int k, int m) { return k * 128 + (m ^ ((k & 3) << 3)); }
template<int BN>
__device__ __forceinline__ int idxB(int k, int n) { return k * BN + (n ^ ((k & 3) << 3)); }

// one BK=16 tile of split-tf32 mma from pre-split uint2 SMEM operands
template<int BN, int NI>
__device__ __forceinline__ void mma_ktile(const uint2* __restrict__ As, const uint2* __restrict__ Bs,
                                          int wm, int wn, int gid, int tig,
                                          float (&acc)[2][NI][4]) {
#pragma unroll
    for (int kk = 0; kk < 2; kk++) {
        const int kb = kk * 8 + tig;
        uint32_t aH[2][4], aL[2][4];
#pragma unroll
        for (int mi = 0; mi < 2; mi++) {
            int r = wm + mi * 16 + gid;
            uint2 v0 = As[idxA(kb,     r    )];
            uint2 v1 = As[idxA(kb,     r + 8)];
            uint2 v2 = As[idxA(kb + 4, r    )];
            uint2 v3 = As[idxA(kb + 4, r + 8)];
            aH[mi][0] = v0.x; aL[mi][0] = v0.y;
            aH[mi][1] = v1.x; aL[mi][1] = v1.y;
            aH[mi][2] = v2.x; aL[mi][2] = v2.y;
            aH[mi][3] = v3.x; aL[mi][3] = v3.y;
        }
#pragma unroll
        for (int ni = 0; ni < NI; ni++) {
            int n = wn + ni * 8 + gid;
            uint2 b0 = Bs[idxB<BN>(kb, n)];
            uint2 b1 = Bs[idxB<BN>(kb + 4, n)];
            uint32_t bh[2] = {b0.x, b1.x};
            uint32_t bl[2] = {b0.y, b1.y};
#pragma unroll
            for (int mi = 0; mi < 2; mi++) {
                mma8(acc[mi][ni], aH[mi], bh);
                mma8(acc[mi][ni], aH[mi], bl);
                mma8(acc[mi][ni], aL[mi], bh);
            }
        }
    }
}

// ---------------- fused feature gather ----------------
__device__ __forceinline__ float gatherA(const float* __restrict__ nf, const float* __restrict__ cfgf,
                                         const int* __restrict__ opc,
                                         const float* __restrict__ opE, const float* __restrict__ tyE,
                                         int n, int c) {
    if (c < 139) return nf[(size_t)n * 140 + c];
    if (c < 143) { int ty = (int)nf[(size_t)n * 140 + 139]; return tyE[ty * 4 + (c - 139)]; }
    if (c < 175) return opE[opc[n] * 32 + (c - 143)];
    if (c < 193) return cfgf[(size_t)n * 18 + (c - 175)];
    return 0.f;
}

// ---------------- initial GEMM: x = relu(gather(feat) @ Wpad + b), (N,128) ----
__global__ __launch_bounds__(256) void gemm_initial(
    const float* __restrict__ nf, const float* __restrict__ cfgf, const int* __restrict__ opc,
    const float* __restrict__ opE, const float* __restrict__ tyE,
    const float* __restrict__ bias, float* __restrict__ X)
{
    constexpr int BN = 128, NI = 8;
    __shared__ uint2 As[16 * 128];
    __shared__ uint2 Bs[16 * BN];
    const int tid = threadIdx.x, lane = tid & 31, wid = tid >> 5;
    const int gid = lane >> 2, tig = lane & 3;
    const int wm = (wid & 3) * 32, wn = (wid >> 2) * (BN / 2);
    const int m0 = blockIdx.x * 128;
    float acc[2][NI][4] = {};

    for (int k0 = 0; k0 < PK; k0 += 16) {
#pragma unroll
        for (int i = 0; i < 8; i++) {
            int idx = tid + i * 256; int m = idx >> 4, k = idx & 15;
            int mg = m0 + m, kg = k0 + k;
            float v = (mg < N_NODES) ? gatherA(nf, cfgf, opc, opE, tyE, mg, kg) : 0.f;
            As[idxA(k, m)] = split2(v);
        }
#pragma unroll
        for (int i = 0; i < 8; i++) {
            int idx = tid + i * 256; int k = idx / BN, n = idx % BN;
            Bs[idxB<BN>(k, n)] = split2(g_wpad[(k0 + k) * 128 + n]);
        }
        __syncthreads();
        mma_ktile<BN, NI>(As, Bs, wm, wn, gid, tig, acc);
        __syncthreads();
    }

#pragma unroll
    for (int mi = 0; mi < 2; mi++) {
        int r0 = m0 + wm + mi * 16 + gid;
#pragma unroll
        for (int ni = 0; ni < NI; ni++) {
            int c = wn + ni * 8 + 2 * tig;
            float b0 = bias[c], b1 = bias[c + 1];
            if (r0 < N_NODES) {
                float2 o = make_float2(fmaxf(acc[mi][ni][0] + b0, 0.f),
                                       fmaxf(acc[mi][ni][1] + b1, 0.f));
                *reinterpret_cast<float2*>(&X[(size_t)r0 * 128 + c]) = o;
            }
            if (r0 + 8 < N_NODES) {
                float2 o = make_float2(fmaxf(acc[mi][ni][2] + b0, 0.f),
                                       fmaxf(acc[mi][ni][3] + b1, 0.f));
                *reinterpret_cast<float2*>(&X[(size_t)(r0 + 8) * 128 + c]) = o;
            }
        }
    }
}

// ---------------- fused layer GEMM ----------------
// Phase 1: [P | agg_init] = [relu(A@wp+bp) | A@wr+bl], P staged (pre-split) in SMEM.
// Phase 2: y = P @ wl.  A optionally scaled per-row by rn.
template<int IND, bool HAS_RN>
__global__ __launch_bounds__(256) void fused_layer(
    const float* __restrict__ Xin, const float* __restrict__ rn,
    const float* __restrict__ wp, const float* __restrict__ bp,
    const float* __restrict__ wr, const float* __restrict__ bl,
    const float* __restrict__ wl,
    float* __restrict__ agg, float* __restrict__ y)
{
    constexpr int BN1 = IND + 64, NI1 = BN1 / 16;
    extern __shared__ uint2 sh[];
    uint2* As = sh;                    // 16*128
    uint2* Bs = As + 16 * 128;         // 16*BN1
    uint2* Ps = Bs + 16 * BN1;         // IND*128
    const int tid = threadIdx.x, lane = tid & 31, wid = tid >> 5;
    const int gid = lane >> 2, tig = lane & 3;
    const int wm = (wid & 3) * 32;
    const int wn1 = (wid >> 2) * (BN1 / 2);
    const int m0 = blockIdx.x * 128;

    // ---- phase 1 ----
    {
        float acc[2][NI1][4] = {};
        for (int k0 = 0; k0 < IND; k0 += 16) {
#pragma unroll
            for (int i = 0; i < 8; i++) {
                int idx = tid + i * 256; int m = idx >> 4, k = idx & 15;
                int mg = m0 + m, kg = k0 + k;
                float v = 0.f;
                if (mg < N_NODES) {
                    v = Xin[(size_t)mg * IND + kg];
                    if (HAS_RN) v *= rn[mg];
                }
                As[idxA(k, m)] = split2(v);
            }
#pragma unroll
            for (int i = 0; i < BN1 / 16; i++) {
                int idx = tid + i * 256; int k = idx / BN1, n = idx % BN1;
                int kg = k0 + k;
                float v = (n < IND) ? wp[kg * IND + n] : wr[kg * 64 + (n - IND)];
                Bs[idxB<BN1>(k, n)] = split2(v);
            }
            __syncthreads();
            mma_ktile<BN1, NI1>(As, Bs, wm, wn1, gid, tig, acc);
            __syncthreads();
        }

        // epilogue: P -> SMEM (pre-split), agg-init -> global
#pragma unroll
        for (int mi = 0; mi < 2; mi++) {
            int lr0 = wm + mi * 16 + gid;
#pragma unroll
            for (int ni = 0; ni < NI1; ni++) {
                int c = wn1 + ni * 8 + 2 * tig;
                float b0, b1;
                if (c < IND) { b0 = bp[c]; b1 = bp[c + 1]; }
                else         { b0 = bl[c - IND]; b1 = bl[c - IND + 1]; }
#pragma unroll
                for (int h = 0; h < 2; h++) {
                    int lr = lr0 + h * 8;
                    float v0 = acc[mi][ni][2 * h]     + b0;
                    float v1 = acc[mi][ni][2 * h + 1] + b1;
                    if (c < IND) {
                        Ps[idxA(c,     lr)] = split2(fmaxf(v0, 0.f));
                        Ps[idxA(c + 1, lr)] = split2(fmaxf(v1, 0.f));
                    } else {
                        int r = m0 + lr;
                        if (r < N_NODES) {
                            float2 o = make_float2(v0, v1);
                            *reinterpret_cast<float2*>(&agg[(size_t)r * 64 + (c - IND)]) = o;
                        }
                    }
                }
            }
        }
    }
    __syncthreads();

    // ---- phase 2: y = P @ wl ----
    {
        constexpr int NI2 = 4;
        const int wn2 = (wid >> 2) * 32;
        float acc[2][NI2][4] = {};
        for (int k0 = 0; k0 < IND; k0 += 16) {
#pragma unroll
            for (int i = 0; i < 4; i++) {
                int idx = tid + i * 256; int k = idx >> 6, n = idx & 63;
                Bs[idxB<64>(k, n)] = split2(wl[(k0 + k) * 64 + n]);
            }
            __syncthreads();
            mma_ktile<64, NI2>(Ps + k0 * 128, Bs, wm, wn2, gid, tig, acc);
            __syncthreads();
        }
#pragma unroll
        for (int mi = 0; mi < 2; mi++) {
            int r0 = m0 + wm + mi * 16 + gid;
#pragma unroll
            for (int ni = 0; ni < NI2; ni++) {
                int c = wn2 + ni * 8 + 2 * tig;
                if (r0 < N_NODES) {
                    float2 o = make_float2(acc[mi][ni][0], acc[mi][ni][1]);
                    *reinterpret_cast<float2*>(&y[(size_t)r0 * 64 + c]) = o;
                }
                if (r0 + 8 < N_NODES) {
                    float2 o = make_float2(acc[mi][ni][2], acc[mi][ni][3]);
                    *reinterpret_cast<float2*>(&y[(size_t)(r0 + 8) * 64 + c]) = o;
                }
            }
        }
    }
}

// ---------------- scatter: agg[dst] += y[src] * deg_inv[dst], 64-wide -------
__global__ void scatter_kernel(const float* __restrict__ y, const int* __restrict__ src,
                               const int* __restrict__ dst, float* __restrict__ agg) {
    size_t t = (size_t)blockIdx.x * blockDim.x + threadIdx.x;
    if (t >= (size_t)E_EDGES * 16) return;
    int e = (int)(t >> 4), q = (int)(t & 15);
    int s = src[e], d = dst[e];
    float4 v = reinterpret_cast<const float4*>(y)[(size_t)s * 16 + q];
    float di = g_deg[d];
    float* p = agg + (size_t)d * 64 + q * 4;
    asm volatile("red.global.add.v4.f32 [%0], {%1,%2,%3,%4};"
                 :: "l"(p), "f"(v.x * di), "f"(v.y * di), "f"(v.z * di), "f"(v.w * di)
                 : "memory");
}

// ---------------- per-row inverse L2 norm ----------------
__global__ void rownorm_kernel(const float* __restrict__ agg) {
    int gw = (blockIdx.x * blockDim.x + threadIdx.x) >> 5;
    int lane = threadIdx.x & 31;
    if (gw >= N_NODES) return;
    float a = agg[(size_t)gw * 64 + lane];
    float b = agg[(size_t)gw * 64 + lane + 32];
    float ss = a * a + b * b;
#pragma unroll
    for (int off = 16; off > 0; off >>= 1) ss += __shfl_xor_sync(0xffffffffu, ss, off);
    if (lane == 0) g_rn[gw] = 1.f / fmaxf(sqrtf(ss), 1e-12f);
}

// ---------------- pooling: direct global atomics ----------
__global__ void pool_kernel(const float* __restrict__ agg, const float* __restrict__ rn,
                            const int* __restrict__ batch) {
    size_t t = (size_t)blockIdx.x * blockDim.x + threadIdx.x;
    if (t >= (size_t)N_NODES * 16) return;
    int n = (int)(t >> 4), q = (int)(t & 15);
    int b = batch[n];
    float4 v = reinterpret_cast<const float4*>(agg)[(size_t)n * 16 + q];
    float r = rn[n];
    v.x *= r; v.y *= r; v.z *= r; v.w *= r;
    int base = b * 64 + q * 4;
    atomicMax(&g_gmax[base + 0], fenc(v.x));
    atomicMax(&g_gmax[base + 1], fenc(v.y));
    atomicMax(&g_gmax[base + 2], fenc(v.z));
    atomicMax(&g_gmax[base + 3], fenc(v.w));
    atomicAdd(&g_gsum[base + 0], v.x);
    atomicAdd(&g_gsum[base + 1], v.y);
    atomicAdd(&g_gsum[base + 2], v.z);
    atomicAdd(&g_gsum[base + 3], v.w);
    if (q == 0) atomicAdd(&g_cnt[b], 1.f);
}

__global__ void final_kernel(const float* __restrict__ pw, const float* __restrict__ pb,
                             float* __restrict__ out) {
    int b = threadIdx.x / 32, lane = threadIdx.x % 32;
    if (b >= NBATCH) return;
    float c = fmaxf(g_cnt[b], 1.f);
    float g0 = fdec(g_gmax[b * 64 + lane])      + g_gsum[b * 64 + lane] / c;
    float g1 = fdec(g_gmax[b * 64 + lane + 32]) + g_gsum[b * 64 + lane + 32] / c;
    float ss = g0 * g0 + g1 * g1;
#pragma unroll
    for (int off = 16; off > 0; off >>= 1) ss += __shfl_xor_sync(0xffffffffu, ss, off);
    float inv = 1.f / sqrtf(ss);
    float o = g0 * inv * pw[lane] + g1 * inv * pw[lane + 32];
#pragma unroll
    for (int off = 16; off > 0; off >>= 1) o += __shfl_xor_sync(0xffffffffu, o, off);
    if (lane == 0) out[b] = o + pb[0];
}

// ---------------- launch ----------------
extern "C" void kernel_launch(void* const* d_in, const int* in_sizes, int n_in,
                              void* d_out, int out_size) {
    const float* node_feat = (const float*)d_in[0];
    const float* cfg       = (const float*)d_in[1];
    const int*   opcode    = (const int*)d_in[2];
    const int*   eidx      = (const int*)d_in[3];
    const int*   batch     = (const int*)d_in[4];
    const float* op_emb    = (const float*)d_in[5];
    const float* type_emb  = (const float*)d_in[6];
    const float* lin_w     = (const float*)d_in[7];
    const float* lin_b     = (const float*)d_in[8];
    const float* post_w    = (const float*)d_in[9];
    const float* post_b    = (const float*)d_in[10];
    const float* wp[3] = {(const float*)d_in[11], (const float*)d_in[16], (const float*)d_in[21]};
    const float* bp[3] = {(const float*)d_in[12], (const float*)d_in[17], (const float*)d_in[22]};
    const float* wl[3] = {(const float*)d_in[13], (const float*)d_in[18], (const float*)d_in[23]};
    const float* bl[3] = {(const float*)d_in[14], (const float*)d_in[19], (const float*)d_in[24]};
    const float* wr[3] = {(const float*)d_in[15], (const float*)d_in[20], (const float*)d_in[25]};
    const int* src = eidx;
    const int* dst = eidx + E_EDGES;

    float *x_, *aggA_, *aggB_, *y_, *rn_, *deg_;
    cudaGetSymbolAddress((void**)&x_,    g_x);
    cudaGetSymbolAddress((void**)&aggA_, g_aggA);
    cudaGetSymbolAddress((void**)&aggB_, g_aggB);
    cudaGetSymbolAddress((void**)&y_,    g_y);
    cudaGetSymbolAddress((void**)&rn_,   g_rn);
    cudaGetSymbolAddress((void**)&deg_,  g_deg);

    const int T = 256;
    const int GEMM_GRID = (N_NODES + 127) / 128;
    const unsigned SCAT_GRID = (unsigned)(((size_t)E_EDGES * 16 + T - 1) / T);
    const unsigned WARP_GRID = (unsigned)(((size_t)N_NODES * 32 + T - 1) / T);
    const unsigned POOL_GRID = (unsigned)(((size_t)N_NODES * 16 + T - 1) / T);

    // dynamic smem sizes for fused layers
    const int SMEM128 = (16 * 128 + 16 * 192 + 128 * 128) * (int)sizeof(uint2); // 172032
    const int SMEM64  = (16 * 128 + 16 * 128 + 64 * 128) * (int)sizeof(uint2);  //  98304
    cudaFuncSetAttribute(fused_layer<128, false>, cudaFuncAttributeMaxDynamicSharedMemorySize, SMEM128);
    cudaFuncSetAttribute(fused_layer<64, true>,   cudaFuncAttributeMaxDynamicSharedMemorySize, SMEM64);

    // init (ordered so gemm_initial lands in the ncu-captured launch slot)
    zero_f<<<(N_NODES + T - 1) / T, T>>>(deg_, N_NODES);
    deg_kernel<<<(E_EDGES + T - 1) / T, T>>>(dst);
    pad_w_kernel<<<(PK * 128 + T - 1) / T, T>>>(lin_w);
    gemm_initial<<<GEMM_GRID, T>>>(node_feat, cfg, opcode, op_emb, type_emb, lin_b, x_);
    deginv_kernel<<<(N_NODES + T - 1) / T, T>>>();
    pool_init_kernel<<<(NBATCH * 64 + T - 1) / T, T>>>();

    // layer 0 (IND=128)
    fused_layer<128, false><<<GEMM_GRID, T, SMEM128>>>(x_, nullptr, wp[0], bp[0], wr[0], bl[0], wl[0], aggA_, y_);
    scatter_kernel<<<SCAT_GRID, T>>>(y_, src, dst, aggA_);
    rownorm_kernel<<<WARP_GRID, T>>>(aggA_);

    // layer 1 (IND=64)
    fused_layer<64, true><<<GEMM_GRID, T, SMEM64>>>(aggA_, rn_, wp[1], bp[1], wr[1], bl[1], wl[1], aggB_, y_);
    scatter_kernel<<<SCAT_GRID, T>>>(y_, src, dst, aggB_);
    rownorm_kernel<<<WARP_GRID, T>>>(aggB_);

    // layer 2 (IND=64)
    fused_layer<64, true><<<GEMM_GRID, T, SMEM64>>>(aggB_, rn_, wp[2], bp[2], wr[2], bl[2], wl[2], aggA_, y_);
    scatter_kernel<<<SCAT_GRID, T>>>(y_, src, dst, aggA_);
    rownorm_kernel<<<WARP_GRID, T>>>(aggA_);

    // pooling on normalized layer-2 output
    pool_kernel<<<POOL_GRID, T>>>(aggA_, rn_, batch);
    final_kernel<<<1, 512>>>(post_w, post_b, (float*)d_out);
}

// round 9
// speedup vs baseline: 1.0396x; 1.0396x over previous
#include <cuda_runtime.h>
#include <math.h>
#include <stdint.h>

#define N_NODES 200000
#define E_EDGES 800000
#define NBATCH  16
#define PK      208   // 193 padded to multiple of 16

// ---------------- scratch (static; no cudaMalloc) ----------------
__device__ __align__(16) float    g_x   [(size_t)N_NODES * 128];
__device__ __align__(16) float    g_xp  [(size_t)N_NODES * 128];
__device__ __align__(16) float    g_aggA[(size_t)N_NODES * 64];
__device__ __align__(16) float    g_aggB[(size_t)N_NODES * 64];
__device__ __align__(16) float    g_y   [(size_t)N_NODES * 64];
__device__ __align__(16) float    g_rn  [N_NODES];
__device__ __align__(16) float    g_deg [N_NODES];
__device__ __align__(16) float    g_wpad[PK * 128];
__device__ __align__(16) unsigned g_gmax[NBATCH * 64];
__device__ __align__(16) float    g_gsum[NBATCH * 64];
__device__ __align__(16) float    g_cnt [NBATCH];

// ---------------- helpers ----------------
__device__ __forceinline__ unsigned fenc(float f) {
    unsigned u = __float_as_uint(f);
    return (u & 0x80000000u) ? ~u : (u | 0x80000000u);
}
__device__ __forceinline__ float fdec(unsigned u) {
    return (u & 0x80000000u) ? __uint_as_float(u & 0x7FFFFFFFu) : __uint_as_float(~u);
}

__global__ void zero_f(float* p, size_t n) {
    size_t i = (size_t)blockIdx.x * blockDim.x + threadIdx.x;
    if (i < n) p[i] = 0.f;
}

__global__ void pool_init_kernel() {
    int i = blockIdx.x * blockDim.x + threadIdx.x;
    if (i < NBATCH * 64) { g_gmax[i] = 0u; g_gsum[i] = 0.f; }
    if (i < NBATCH) g_cnt[i] = 0.f;
}

__global__ void pad_w_kernel(const float* __restrict__ lin_w) {
    int t = blockIdx.x * blockDim.x + threadIdx.x;
    if (t >= PK * 128) return;
    int k = t / 128, j = t % 128;
    g_wpad[t] = (k < 193) ? lin_w[k * 128 + j] : 0.f;
}

__global__ void deg_kernel(const int* __restrict__ dst) {
    int e = blockIdx.x * blockDim.x + threadIdx.x;
    if (e < E_EDGES) atomicAdd(&g_deg[dst[e]], 1.f);
}
__global__ void deginv_kernel() {
    int n = blockIdx.x * blockDim.x + threadIdx.x;
    if (n < N_NODES) g_deg[n] = 1.f / fmaxf(g_deg[n], 1.f);
}

// ---------------- tf32 split helpers ----------------
__device__ __forceinline__ uint2 split2(float x) {
    uint32_t hb;
    asm("cvt.rna.tf32.f32 %0, %1;" : "=r"(hb) : "f"(x));
    return make_uint2(hb, __float_as_uint(x - __uint_as_float(hb)));
}

__device__ __forceinline__ void mma8(float* c, const uint32_t* a, const uint32_t* b) {
    asm("mma.sync.aligned.m16n8k8.row.col.f32.tf32.tf32.f32 "
        "{%0,%1,%2,%3}, {%4,%5,%6,%7}, {%8,%9}, {%0,%1,%2,%3};"
        : "+f"(c[0]), "+f"(c[1]), "+f"(c[2]), "+f"(c[3])
        : "r"(a[0]), "r"(a[1]), "r"(a[2]), "r"(a[3]), "r"(b[0]), "r"(b[1]));
}

// swizzled indices (BM=64 A-tile, arbitrary-BN B-tile), uint2 arrays
__device__ __forceinline__ int idxA(int k, int m) { return k * 64 + (m ^ ((k & 3) << 3)); }
template<int BN>
__device__ __forceinline__ int idxB(int k, int n) { return k * BN + (n ^ ((k & 3) << 3)); }

// one BK=16 tile of split-tf32 mma; block tile 64 x BN, 8 warps as 2M x 4N.
// warp tile: 32 rows (2 x m16) x (BN/4) cols (NI x n8).
template<int BN, int NI>
__device__ __forceinline__ void mma_ktile(const uint2* __restrict__ As, const uint2* __restrict__ Bs,
                                          int wm, int wn, int gid, int tig,
                                          float (&acc)[2][NI][4]) {
#pragma unroll
    for (int kk = 0; kk < 2; kk++) {
        const int kb = kk * 8 + tig;
        uint32_t aH[2][4], aL[2][4];
#pragma unroll
        for (int mi = 0; mi < 2; mi++) {
            int r = wm + mi * 16 + gid;
            uint2 v0 = As[idxA(kb,     r    )];
            uint2 v1 = As[idxA(kb,     r + 8)];
            uint2 v2 = As[idxA(kb + 4, r    )];
            uint2 v3 = As[idxA(kb + 4, r + 8)];
            aH[mi][0] = v0.x; aL[mi][0] = v0.y;
            aH[mi][1] = v1.x; aL[mi][1] = v1.y;
            aH[mi][2] = v2.x; aL[mi][2] = v2.y;
            aH[mi][3] = v3.x; aL[mi][3] = v3.y;
        }
#pragma unroll
        for (int ni = 0; ni < NI; ni++) {
            int n = wn + ni * 8 + gid;
            uint2 b0 = Bs[idxB<BN>(kb, n)];
            uint2 b1 = Bs[idxB<BN>(kb + 4, n)];
            uint32_t bh[2] = {b0.x, b1.x};
            uint32_t bl[2] = {b0.y, b1.y};
#pragma unroll
            for (int mi = 0; mi < 2; mi++) {
                mma8(acc[mi][ni], aH[mi], bh);
                mma8(acc[mi][ni], aH[mi], bl);
                mma8(acc[mi][ni], aL[mi], bh);
            }
        }
    }
}

// ---------------- fused feature gather ----------------
__device__ __forceinline__ float gatherA(const float* __restrict__ nf, const float* __restrict__ cfgf,
                                         const int* __restrict__ opc,
                                         const float* __restrict__ opE, const float* __restrict__ tyE,
                                         int n, int c) {
    if (c < 139) return nf[(size_t)n * 140 + c];
    if (c < 143) { int ty = (int)nf[(size_t)n * 140 + 139]; return tyE[ty * 4 + (c - 139)]; }
    if (c < 175) return opE[opc[n] * 32 + (c - 143)];
    if (c < 193) return cfgf[(size_t)n * 18 + (c - 175)];
    return 0.f;
}

// ---------------- initial GEMM: x = relu(gather(feat) @ Wpad + b), (N,128) ----
// BM=64, BN=128, 8 warps (2M x 4N), NI=4.
__global__ __launch_bounds__(256) void gemm_initial(
    const float* __restrict__ nf, const float* __restrict__ cfgf, const int* __restrict__ opc,
    const float* __restrict__ opE, const float* __restrict__ tyE,
    const float* __restrict__ bias, float* __restrict__ X)
{
    constexpr int BN = 128, NI = 4;
    __shared__ uint2 As[16 * 64];
    __shared__ uint2 Bs[16 * BN];
    const int tid = threadIdx.x, lane = tid & 31, wid = tid >> 5;
    const int gid = lane >> 2, tig = lane & 3;
    const int wm = (wid & 1) * 32, wn = (wid >> 1) * (BN / 4);
    const int m0 = blockIdx.x * 64;
    float acc[2][NI][4] = {};

    for (int k0 = 0; k0 < PK; k0 += 16) {
#pragma unroll
        for (int i = 0; i < 4; i++) {
            int idx = tid + i * 256; int m = idx >> 4, k = idx & 15;
            int mg = m0 + m, kg = k0 + k;
            float v = (mg < N_NODES) ? gatherA(nf, cfgf, opc, opE, tyE, mg, kg) : 0.f;
            As[idxA(k, m)] = split2(v);
        }
#pragma unroll
        for (int i = 0; i < 8; i++) {
            int idx = tid + i * 256; int k = idx / BN, n = idx % BN;
            Bs[idxB<BN>(k, n)] = split2(g_wpad[(k0 + k) * 128 + n]);
        }
        __syncthreads();
        mma_ktile<BN, NI>(As, Bs, wm, wn, gid, tig, acc);
        __syncthreads();
    }

#pragma unroll
    for (int mi = 0; mi < 2; mi++) {
        int r0 = m0 + wm + mi * 16 + gid;
#pragma unroll
        for (int ni = 0; ni < NI; ni++) {
            int c = wn + ni * 8 + 2 * tig;
            float b0 = bias[c], b1 = bias[c + 1];
            if (r0 < N_NODES) {
                float2 o = make_float2(fmaxf(acc[mi][ni][0] + b0, 0.f),
                                       fmaxf(acc[mi][ni][1] + b1, 0.f));
                *reinterpret_cast<float2*>(&X[(size_t)r0 * 128 + c]) = o;
            }
            if (r0 + 8 < N_NODES) {
                float2 o = make_float2(fmaxf(acc[mi][ni][2] + b0, 0.f),
                                       fmaxf(acc[mi][ni][3] + b1, 0.f));
                *reinterpret_cast<float2*>(&X[(size_t)(r0 + 8) * 128 + c]) = o;
            }
        }
    }
}

// ---------------- GEMM1: [xp | agg_init] = [relu(A@wp+bp) | A@wr+bl] --------
// BM=64, BN=IND+64, 8 warps (2M x 4N), NI=BN/32.
template<int IND, bool HAS_RN>
__global__ __launch_bounds__(256) void gemm1_kernel(
    const float* __restrict__ Xin, const float* __restrict__ rn,
    const float* __restrict__ wp, const float* __restrict__ bp,
    const float* __restrict__ wr, const float* __restrict__ bl,
    float* __restrict__ xp, float* __restrict__ agg)
{
    constexpr int BN = IND + 64, NI = BN / 32;
    __shared__ uint2 As[16 * 64];
    __shared__ uint2 Bs[16 * BN];
    const int tid = threadIdx.x, lane = tid & 31, wid = tid >> 5;
    const int gid = lane >> 2, tig = lane & 3;
    const int wm = (wid & 1) * 32, wn = (wid >> 1) * (BN / 4);
    const int m0 = blockIdx.x * 64;
    float acc[2][NI][4] = {};

    for (int k0 = 0; k0 < IND; k0 += 16) {
#pragma unroll
        for (int i = 0; i < 4; i++) {
            int idx = tid + i * 256; int m = idx >> 4, k = idx & 15;
            int mg = m0 + m, kg = k0 + k;
            float v = 0.f;
            if (mg < N_NODES) {
                v = Xin[(size_t)mg * IND + kg];
                if (HAS_RN) v *= rn[mg];
            }
            As[idxA(k, m)] = split2(v);
        }
#pragma unroll
        for (int i = 0; i < BN / 16; i++) {
            int idx = tid + i * 256; int k = idx / BN, n = idx % BN;
            int kg = k0 + k;
            float v = (n < IND) ? wp[kg * IND + n] : wr[kg * 64 + (n - IND)];
            Bs[idxB<BN>(k, n)] = split2(v);
        }
        __syncthreads();
        mma_ktile<BN, NI>(As, Bs, wm, wn, gid, tig, acc);
        __syncthreads();
    }

#pragma unroll
    for (int mi = 0; mi < 2; mi++) {
        int r0 = m0 + wm + mi * 16 + gid;
#pragma unroll
        for (int ni = 0; ni < NI; ni++) {
            int c = wn + ni * 8 + 2 * tig;
            float b0, b1;
            if (c < IND) { b0 = bp[c]; b1 = bp[c + 1]; }
            else         { b0 = bl[c - IND]; b1 = bl[c - IND + 1]; }
#pragma unroll
            for (int h = 0; h < 2; h++) {
                int r = r0 + h * 8;
                if (r >= N_NODES) continue;
                float v0 = acc[mi][ni][2 * h]     + b0;
                float v1 = acc[mi][ni][2 * h + 1] + b1;
                if (c < IND) {
                    float2 o = make_float2(fmaxf(v0, 0.f), fmaxf(v1, 0.f));
                    *reinterpret_cast<float2*>(&xp[(size_t)r * IND + c]) = o;
                } else {
                    float2 o = make_float2(v0, v1);
                    *reinterpret_cast<float2*>(&agg[(size_t)r * 64 + (c - IND)]) = o;
                }
            }
        }
    }
}

// ---------------- GEMM2: y = xp @ wl, (N,64) ----------------
// BM=64, BN=64, 8 warps (2M x 4N), NI=2.
template<int IND>
__global__ __launch_bounds__(256) void gemm2_kernel(
    const float* __restrict__ xp, const float* __restrict__ wl, float* __restrict__ y)
{
    constexpr int BN = 64, NI = 2;
    __shared__ uint2 As[16 * 64];
    __shared__ uint2 Bs[16 * BN];
    const int tid = threadIdx.x, lane = tid & 31, wid = tid >> 5;
    const int gid = lane >> 2, tig = lane & 3;
    const int wm = (wid & 1) * 32, wn = (wid >> 1) * 16;
    const int m0 = blockIdx.x * 64;
    float acc[2][NI][4] = {};

    for (int k0 = 0; k0 < IND; k0 += 16) {
#pragma unroll
        for (int i = 0; i < 4; i++) {
            int idx = tid + i * 256; int m = idx >> 4, k = idx & 15;
            int mg = m0 + m, kg = k0 + k;
            As[idxA(k, m)] = split2((mg < N_NODES) ? xp[(size_t)mg * IND + kg] : 0.f);
        }
#pragma unroll
        for (int i = 0; i < 4; i++) {
            int idx = tid + i * 256; int k = idx >> 6, n = idx & 63;
            Bs[idxB<BN>(k, n)] = split2(wl[(k0 + k) * 64 + n]);
        }
        __syncthreads();
        mma_ktile<BN, NI>(As, Bs, wm, wn, gid, tig, acc);
        __syncthreads();
    }
#pragma unroll
    for (int mi = 0; mi < 2; mi++) {
        int r0 = m0 + wm + mi * 16 + gid;
#pragma unroll
        for (int ni = 0; ni < NI; ni++) {
            int c = wn + ni * 8 + 2 * tig;
            if (r0 < N_NODES) {
                float2 o = make_float2(acc[mi][ni][0], acc[mi][ni][1]);
                *reinterpret_cast<float2*>(&y[(size_t)r0 * 64 + c]) = o;
            }
            if (r0 + 8 < N_NODES) {
                float2 o = make_float2(acc[mi][ni][2], acc[mi][ni][3]);
                *reinterpret_cast<float2*>(&y[(size_t)(r0 + 8) * 64 + c]) = o;
            }
        }
    }
}

// ---------------- scatter: agg[dst] += y[src] * deg_inv[dst], 64-wide -------
__global__ void scatter_kernel(const float* __restrict__ y, const int* __restrict__ src,
                               const int* __restrict__ dst, float* __restrict__ agg) {
    size_t t = (size_t)blockIdx.x * blockDim.x + threadIdx.x;
    if (t >= (size_t)E_EDGES * 16) return;
    int e = (int)(t >> 4), q = (int)(t & 15);
    int s = src[e], d = dst[e];
    float4 v = reinterpret_cast<const float4*>(y)[(size_t)s * 16 + q];
    float di = g_deg[d];
    float* p = agg + (size_t)d * 64 + q * 4;
    asm volatile("red.global.add.v4.f32 [%0], {%1,%2,%3,%4};"
                 :: "l"(p), "f"(v.x * di), "f"(v.y * di), "f"(v.z * di), "f"(v.w * di)
                 : "memory");
}

// ---------------- per-row inverse L2 norm ----------------
__global__ void rownorm_kernel(const float* __restrict__ agg) {
    int gw = (blockIdx.x * blockDim.x + threadIdx.x) >> 5;
    int lane = threadIdx.x & 31;
    if (gw >= N_NODES) return;
    float a = agg[(size_t)gw * 64 + lane];
    float b = agg[(size_t)gw * 64 + lane + 32];
    float ss = a * a + b * b;
#pragma unroll
    for (int off = 16; off > 0; off >>= 1) ss += __shfl_xor_sync(0xffffffffu, ss, off);
    if (lane == 0) g_rn[gw] = 1.f / fmaxf(sqrtf(ss), 1e-12f);
}

// ---------------- pooling: direct global atomics ----------
__global__ void pool_kernel(const float* __restrict__ agg, const float* __restrict__ rn,
                            const int* __restrict__ batch) {
    size_t t = (size_t)blockIdx.x * blockDim.x + threadIdx.x;
    if (t >= (size_t)N_NODES * 16) return;
    int n = (int)(t >> 4), q = (int)(t & 15);
    int b = batch[n];
    float4 v = reinterpret_cast<const float4*>(agg)[(size_t)n * 16 + q];
    float r = rn[n];
    v.x *= r; v.y *= r; v.z *= r; v.w *= r;
    int base = b * 64 + q * 4;
    atomicMax(&g_gmax[base + 0], fenc(v.x));
    atomicMax(&g_gmax[base + 1], fenc(v.y));
    atomicMax(&g_gmax[base + 2], fenc(v.z));
    atomicMax(&g_gmax[base + 3], fenc(v.w));
    atomicAdd(&g_gsum[base + 0], v.x);
    atomicAdd(&g_gsum[base + 1], v.y);
    atomicAdd(&g_gsum[base + 2], v.z);
    atomicAdd(&g_gsum[base + 3], v.w);
    if (q == 0) atomicAdd(&g_cnt[b], 1.f);
}

__global__ void final_kernel(const float* __restrict__ pw, const float* __restrict__ pb,
                             float* __restrict__ out) {
    int b = threadIdx.x / 32, lane = threadIdx.x % 32;
    if (b >= NBATCH) return;
    float c = fmaxf(g_cnt[b], 1.f);
    float g0 = fdec(g_gmax[b * 64 + lane])      + g_gsum[b * 64 + lane] / c;
    float g1 = fdec(g_gmax[b * 64 + lane + 32]) + g_gsum[b * 64 + lane + 32] / c;
    float ss = g0 * g0 + g1 * g1;
#pragma unroll
    for (int off = 16; off > 0; off >>= 1) ss += __shfl_xor_sync(0xffffffffu, ss, off);
    float inv = 1.f / sqrtf(ss);
    float o = g0 * inv * pw[lane] + g1 * inv * pw[lane + 32];
#pragma unroll
    for (int off = 16; off > 0; off >>= 1) o += __shfl_xor_sync(0xffffffffu, o, off);
    if (lane == 0) out[b] = o + pb[0];
}

// ---------------- launch ----------------
extern "C" void kernel_launch(void* const* d_in, const int* in_sizes, int n_in,
                              void* d_out, int out_size) {
    const float* node_feat = (const float*)d_in[0];
    const float* cfg       = (const float*)d_in[1];
    const int*   opcode    = (const int*)d_in[2];
    const int*   eidx      = (const int*)d_in[3];
    const int*   batch     = (const int*)d_in[4];
    const float* op_emb    = (const float*)d_in[5];
    const float* type_emb  = (const float*)d_in[6];
    const float* lin_w     = (const float*)d_in[7];
    const float* lin_b     = (const float*)d_in[8];
    const float* post_w    = (const float*)d_in[9];
    const float* post_b    = (const float*)d_in[10];
    const float* wp[3] = {(const float*)d_in[11], (const float*)d_in[16], (const float*)d_in[21]};
    const float* bp[3] = {(const float*)d_in[12], (const float*)d_in[17], (const float*)d_in[22]};
    const float* wl[3] = {(const float*)d_in[13], (const float*)d_in[18], (const float*)d_in[23]};
    const float* bl[3] = {(const float*)d_in[14], (const float*)d_in[19], (const float*)d_in[24]};
    const float* wr[3] = {(const float*)d_in[15], (const float*)d_in[20], (const float*)d_in[25]};
    const int* src = eidx;
    const int* dst = eidx + E_EDGES;

    float *x_, *xp_, *aggA_, *aggB_, *y_, *rn_, *deg_;
    cudaGetSymbolAddress((void**)&x_,    g_x);
    cudaGetSymbolAddress((void**)&xp_,   g_xp);
    cudaGetSymbolAddress((void**)&aggA_, g_aggA);
    cudaGetSymbolAddress((void**)&aggB_, g_aggB);
    cudaGetSymbolAddress((void**)&y_,    g_y);
    cudaGetSymbolAddress((void**)&rn_,   g_rn);
    cudaGetSymbolAddress((void**)&deg_,  g_deg);

    const int T = 256;
    const int GEMM_GRID = (N_NODES + 63) / 64;   // BM=64
    const unsigned SCAT_GRID = (unsigned)(((size_t)E_EDGES * 16 + T - 1) / T);
    const unsigned WARP_GRID = (unsigned)(((size_t)N_NODES * 32 + T - 1) / T);
    const unsigned POOL_GRID = (unsigned)(((size_t)N_NODES * 16 + T - 1) / T);

    // init (ordered so gemm_initial lands in the ncu-captured launch slot)
    zero_f<<<(N_NODES + T - 1) / T, T>>>(deg_, N_NODES);
    deg_kernel<<<(E_EDGES + T - 1) / T, T>>>(dst);
    pad_w_kernel<<<(PK * 128 + T - 1) / T, T>>>(lin_w);
    gemm_initial<<<GEMM_GRID, T>>>(node_feat, cfg, opcode, op_emb, type_emb, lin_b, x_);
    deginv_kernel<<<(N_NODES + T - 1) / T, T>>>();
    pool_init_kernel<<<(NBATCH * 64 + T - 1) / T, T>>>();

    // layer 0 (IND=128)
    gemm1_kernel<128, false><<<GEMM_GRID, T>>>(x_, nullptr, wp[0], bp[0], wr[0], bl[0], xp_, aggA_);
    gemm2_kernel<128><<<GEMM_GRID, T>>>(xp_, wl[0], y_);
    scatter_kernel<<<SCAT_GRID, T>>>(y_, src, dst, aggA_);
    rownorm_kernel<<<WARP_GRID, T>>>(aggA_);

    // layer 1 (IND=64)
    gemm1_kernel<64, true><<<GEMM_GRID, T>>>(aggA_, rn_, wp[1], bp[1], wr[1], bl[1], xp_, aggB_);
    gemm2_kernel<64><<<GEMM_GRID, T>>>(xp_, wl[1], y_);
    scatter_kernel<<<SCAT_GRID, T>>>(y_, src, dst, aggB_);
    rownorm_kernel<<<WARP_GRID, T>>>(aggB_);

    // layer 2 (IND=64)
    gemm1_kernel<64, true><<<GEMM_GRID, T>>>(aggB_, rn_, wp[2], bp[2], wr[2], bl[2], xp_, aggA_);
    gemm2_kernel<64><<<GEMM_GRID, T>>>(xp_, wl[2], y_);
    scatter_kernel<<<SCAT_GRID, T>>>(y_, src, dst, aggA_);
    rownorm_kernel<<<WARP_GRID, T>>>(aggA_);

    // pooling on normalized layer-2 output
    pool_kernel<<<POOL_GRID, T>>>(aggA_, rn_, batch);
    final_kernel<<<1, 512>>>(post_w, post_b, (float*)d_out);
}

// round 11
// speedup vs baseline: 1.1450x; 1.1014x over previous
#include <cuda_runtime.h>
#include <math.h>
#include <stdint.h>

#define N_NODES 200000
#define E_EDGES 800000
#define NBATCH  16
#define PK      208   // 193 padded to multiple of 16

// ---------------- scratch (static; no cudaMalloc) ----------------
__device__ __align__(16) float    g_x   [(size_t)N_NODES * 128];
__device__ __align__(16) float    g_xp  [(size_t)N_NODES * 128];
__device__ __align__(16) float    g_aggA[(size_t)N_NODES * 64];
__device__ __align__(16) float    g_aggB[(size_t)N_NODES * 64];
__device__ __align__(16) float    g_y   [(size_t)N_NODES * 64];
__device__ __align__(16) float    g_rn  [N_NODES];
__device__ __align__(16) float    g_deg [N_NODES];
__device__ __align__(16) float    g_wpad[PK * 128];
__device__ __align__(16) unsigned g_gmax[NBATCH * 64];
__device__ __align__(16) float    g_gsum[NBATCH * 64];
__device__ __align__(16) float    g_cnt [NBATCH];

// ---------------- helpers ----------------
__device__ __forceinline__ unsigned fenc(float f) {
    unsigned u = __float_as_uint(f);
    return (u & 0x80000000u) ? ~u : (u | 0x80000000u);
}
__device__ __forceinline__ float fdec(unsigned u) {
    return (u & 0x80000000u) ? __uint_as_float(u & 0x7FFFFFFFu) : __uint_as_float(~u);
}

__global__ void zero_f(float* p, size_t n) {
    size_t i = (size_t)blockIdx.x * blockDim.x + threadIdx.x;
    if (i < n) p[i] = 0.f;
}

__global__ void pool_init_kernel() {
    int i = blockIdx.x * blockDim.x + threadIdx.x;
    if (i < NBATCH * 64) { g_gmax[i] = 0u; g_gsum[i] = 0.f; }
    if (i < NBATCH) g_cnt[i] = 0.f;
}

__global__ void pad_w_kernel(const float* __restrict__ lin_w) {
    int t = blockIdx.x * blockDim.x + threadIdx.x;
    if (t >= PK * 128) return;
    int k = t / 128, j = t % 128;
    g_wpad[t] = (k < 193) ? lin_w[k * 128 + j] : 0.f;
}

__global__ void deg_kernel(const int* __restrict__ dst) {
    int e = blockIdx.x * blockDim.x + threadIdx.x;
    if (e < E_EDGES) atomicAdd(&g_deg[dst[e]], 1.f);
}
__global__ void deginv_kernel() {
    int n = blockIdx.x * blockDim.x + threadIdx.x;
    if (n < N_NODES) g_deg[n] = 1.f / fmaxf(g_deg[n], 1.f);
}

// ---------------- tf32 split helpers ----------------
__device__ __forceinline__ void split_tf32(float x, uint32_t& h, uint32_t& l) {
    uint32_t hb;
    asm("cvt.rna.tf32.f32 %0, %1;" : "=r"(hb) : "f"(x));
    h = hb;
    l = __float_as_uint(x - __uint_as_float(hb));
}

__device__ __forceinline__ void mma8(float* c, const uint32_t* a, const uint32_t* b) {
    asm("mma.sync.aligned.m16n8k8.row.col.f32.tf32.tf32.f32 "
        "{%0,%1,%2,%3}, {%4,%5,%6,%7}, {%8,%9}, {%0,%1,%2,%3};"
        : "+f"(c[0]), "+f"(c[1]), "+f"(c[2]), "+f"(c[3])
        : "r"(a[0]), "r"(a[1]), "r"(a[2]), "r"(a[3]), "r"(b[0]), "r"(b[1]));
}

// conflict-free swizzled indices (BM=64 A-tile; 4-byte elements)
__device__ __forceinline__ int idxA(int k, int m) { return k * 64 + (m ^ ((k & 3) << 3)); }
template<int BN>
__device__ __forceinline__ int idxB(int k, int n) { return k * BN + (n ^ ((k & 3) << 3)); }

// one BK=16 tile of split-tf32 mma; block tile 64 x BN, 8 warps as 2M x 4N.
// A in fp32 SMEM (split in registers); B pre-split in separate Bh/Bl arrays.
template<int BN, int NI>
__device__ __forceinline__ void mma_ktile(const float* __restrict__ As,
                                          const uint32_t* __restrict__ Bh,
                                          const uint32_t* __restrict__ Bl,
                                          int wm, int wn, int gid, int tig,
                                          float (&acc)[2][NI][4]) {
#pragma unroll
    for (int kk = 0; kk < 2; kk++) {
        const int kb = kk * 8 + tig;
        uint32_t aH[2][4], aL[2][4];
#pragma unroll
        for (int mi = 0; mi < 2; mi++) {
            int r = wm + mi * 16 + gid;
            split_tf32(As[idxA(kb,     r    )], aH[mi][0], aL[mi][0]);
            split_tf32(As[idxA(kb,     r + 8)], aH[mi][1], aL[mi][1]);
            split_tf32(As[idxA(kb + 4, r    )], aH[mi][2], aL[mi][2]);
            split_tf32(As[idxA(kb + 4, r + 8)], aH[mi][3], aL[mi][3]);
        }
#pragma unroll
        for (int ni = 0; ni < NI; ni++) {
            int n = wn + ni * 8 + gid;
            uint32_t bh[2], bl[2];
            bh[0] = Bh[idxB<BN>(kb, n)];     bh[1] = Bh[idxB<BN>(kb + 4, n)];
            bl[0] = Bl[idxB<BN>(kb, n)];     bl[1] = Bl[idxB<BN>(kb + 4, n)];
#pragma unroll
            for (int mi = 0; mi < 2; mi++) {
                mma8(acc[mi][ni], aH[mi], bh);
                mma8(acc[mi][ni], aH[mi], bl);
                mma8(acc[mi][ni], aL[mi], bh);
            }
        }
    }
}

// ---------------- fused feature gather ----------------
__device__ __forceinline__ float gatherA(const float* __restrict__ nf, const float* __restrict__ cfgf,
                                         const int* __restrict__ opc,
                                         const float* __restrict__ opE, const float* __restrict__ tyE,
                                         int n, int c) {
    if (c < 139) return nf[(size_t)n * 140 + c];
    if (c < 143) { int ty = (int)nf[(size_t)n * 140 + 139]; return tyE[ty * 4 + (c - 139)]; }
    if (c < 175) return opE[opc[n] * 32 + (c - 143)];
    if (c < 193) return cfgf[(size_t)n * 18 + (c - 175)];
    return 0.f;
}

// ---------------- initial GEMM: x = relu(gather(feat) @ Wpad + b), (N,128) ----
// BM=64, BN=128, 8 warps (2M x 4N), NI=4.
__global__ __launch_bounds__(256) void gemm_initial(
    const float* __restrict__ nf, const float* __restrict__ cfgf, const int* __restrict__ opc,
    const float* __restrict__ opE, const float* __restrict__ tyE,
    const float* __restrict__ bias, float* __restrict__ X)
{
    constexpr int BN = 128, NI = 4;
    __shared__ float    As[16 * 64];
    __shared__ uint32_t Bh[16 * BN];
    __shared__ uint32_t Bl[16 * BN];
    const int tid = threadIdx.x, lane = tid & 31, wid = tid >> 5;
    const int gid = lane >> 2, tig = lane & 3;
    const int wm = (wid & 1) * 32, wn = (wid >> 1) * (BN / 4);
    const int m0 = blockIdx.x * 64;
    float acc[2][NI][4] = {};

    for (int k0 = 0; k0 < PK; k0 += 16) {
#pragma unroll
        for (int i = 0; i < 4; i++) {
            int idx = tid + i * 256; int m = idx >> 4, k = idx & 15;
            int mg = m0 + m, kg = k0 + k;
            float v = (mg < N_NODES) ? gatherA(nf, cfgf, opc, opE, tyE, mg, kg) : 0.f;
            As[idxA(k, m)] = v;
        }
#pragma unroll
        for (int i = 0; i < 8; i++) {
            int idx = tid + i * 256; int k = idx / BN, n = idx % BN;
            uint32_t h, l;
            split_tf32(g_wpad[(k0 + k) * 128 + n], h, l);
            Bh[idxB<BN>(k, n)] = h; Bl[idxB<BN>(k, n)] = l;
        }
        __syncthreads();
        mma_ktile<BN, NI>(As, Bh, Bl, wm, wn, gid, tig, acc);
        __syncthreads();
    }

#pragma unroll
    for (int mi = 0; mi < 2; mi++) {
        int r0 = m0 + wm + mi * 16 + gid;
#pragma unroll
        for (int ni = 0; ni < NI; ni++) {
            int c = wn + ni * 8 + 2 * tig;
            float b0 = bias[c], b1 = bias[c + 1];
            if (r0 < N_NODES) {
                float2 o = make_float2(fmaxf(acc[mi][ni][0] + b0, 0.f),
                                       fmaxf(acc[mi][ni][1] + b1, 0.f));
                *reinterpret_cast<float2*>(&X[(size_t)r0 * 128 + c]) = o;
            }
            if (r0 + 8 < N_NODES) {
                float2 o = make_float2(fmaxf(acc[mi][ni][2] + b0, 0.f),
                                       fmaxf(acc[mi][ni][3] + b1, 0.f));
                *reinterpret_cast<float2*>(&X[(size_t)(r0 + 8) * 128 + c]) = o;
            }
        }
    }
}

// ---------------- GEMM1: [xp | agg_init] = [relu(A@wp+bp) | A@wr+bl] --------
// BM=64, BN=IND+64, 8 warps (2M x 4N), NI=BN/32.
template<int IND, bool HAS_RN>
__global__ __launch_bounds__(256) void gemm1_kernel(
    const float* __restrict__ Xin, const float* __restrict__ rn,
    const float* __restrict__ wp, const float* __restrict__ bp,
    const float* __restrict__ wr, const float* __restrict__ bl,
    float* __restrict__ xp, float* __restrict__ agg)
{
    constexpr int BN = IND + 64, NI = BN / 32;
    __shared__ float    As[16 * 64];
    __shared__ uint32_t Bh[16 * BN];
    __shared__ uint32_t Bl[16 * BN];
    const int tid = threadIdx.x, lane = tid & 31, wid = tid >> 5;
    const int gid = lane >> 2, tig = lane & 3;
    const int wm = (wid & 1) * 32, wn = (wid >> 1) * (BN / 4);
    const int m0 = blockIdx.x * 64;
    float acc[2][NI][4] = {};

    for (int k0 = 0; k0 < IND; k0 += 16) {
#pragma unroll
        for (int i = 0; i < 4; i++) {
            int idx = tid + i * 256; int m = idx >> 4, k = idx & 15;
            int mg = m0 + m, kg = k0 + k;
            float v = 0.f;
            if (mg < N_NODES) {
                v = Xin[(size_t)mg * IND + kg];
                if (HAS_RN) v *= rn[mg];
            }
            As[idxA(k, m)] = v;
        }
#pragma unroll
        for (int i = 0; i < BN / 16; i++) {
            int idx = tid + i * 256; int k = idx / BN, n = idx % BN;
            int kg = k0 + k;
            float v = (n < IND) ? wp[kg * IND + n] : wr[kg * 64 + (n - IND)];
            uint32_t h, l; split_tf32(v, h, l);
            Bh[idxB<BN>(k, n)] = h; Bl[idxB<BN>(k, n)] = l;
        }
        __syncthreads();
        mma_ktile<BN, NI>(As, Bh, Bl, wm, wn, gid, tig, acc);
        __syncthreads();
    }

#pragma unroll
    for (int mi = 0; mi < 2; mi++) {
        int r0 = m0 + wm + mi * 16 + gid;
#pragma unroll
        for (int ni = 0; ni < NI; ni++) {
            int c = wn + ni * 8 + 2 * tig;
            float b0, b1;
            if (c < IND) { b0 = bp[c]; b1 = bp[c + 1]; }
            else         { b0 = bl[c - IND]; b1 = bl[c - IND + 1]; }
#pragma unroll
            for (int h = 0; h < 2; h++) {
                int r = r0 + h * 8;
                if (r >= N_NODES) continue;
                float v0 = acc[mi][ni][2 * h]     + b0;
                float v1 = acc[mi][ni][2 * h + 1] + b1;
                if (c < IND) {
                    float2 o = make_float2(fmaxf(v0, 0.f), fmaxf(v1, 0.f));
                    *reinterpret_cast<float2*>(&xp[(size_t)r * IND + c]) = o;
                } else {
                    float2 o = make_float2(v0, v1);
                    *reinterpret_cast<float2*>(&agg[(size_t)r * 64 + (c - IND)]) = o;
                }
            }
        }
    }
}

// ---------------- GEMM2: y = xp @ wl, (N,64) ----------------
// BM=64, BN=64, 8 warps (2M x 4N), NI=2.
template<int IND>
__global__ __launch_bounds__(256) void gemm2_kernel(
    const float* __restrict__ xp, const float* __restrict__ wl, float* __restrict__ y)
{
    constexpr int BN = 64, NI = 2;
    __shared__ float    As[16 * 64];
    __shared__ uint32_t Bh[16 * BN];
    __shared__ uint32_t Bl[16 * BN];
    const int tid = threadIdx.x, lane = tid & 31, wid = tid >> 5;
    const int gid = lane >> 2, tig = lane & 3;
    const int wm = (wid & 1) * 32, wn = (wid >> 1) * 16;
    const int m0 = blockIdx.x * 64;
    float acc[2][NI][4] = {};

    for (int k0 = 0; k0 < IND; k0 += 16) {
#pragma unroll
        for (int i = 0; i < 4; i++) {
            int idx = tid + i * 256; int m = idx >> 4, k = idx & 15;
            int mg = m0 + m, kg = k0 + k;
            As[idxA(k, m)] = (mg < N_NODES) ? xp[(size_t)mg * IND + kg] : 0.f;
        }
#pragma unroll
        for (int i = 0; i < 4; i++) {
            int idx = tid + i * 256; int k = idx >> 6, n = idx & 63;
            uint32_t h, l; split_tf32(wl[(k0 + k) * 64 + n], h, l);
            Bh[idxB<BN>(k, n)] = h; Bl[idxB<BN>(k, n)] = l;
        }
        __syncthreads();
        mma_ktile<BN, NI>(As, Bh, Bl, wm, wn, gid, tig, acc);
        __syncthreads();
    }
#pragma unroll
    for (int mi = 0; mi < 2; mi++) {
        int r0 = m0 + wm + mi * 16 + gid;
#pragma unroll
        for (int ni = 0; ni < NI; ni++) {
            int c = wn + ni * 8 + 2 * tig;
            if (r0 < N_NODES) {
                float2 o = make_float2(acc[mi][ni][0], acc[mi][ni][1]);
                *reinterpret_cast<float2*>(&y[(size_t)r0 * 64 + c]) = o;
            }
            if (r0 + 8 < N_NODES) {
                float2 o = make_float2(acc[mi][ni][2], acc[mi][ni][3]);
                *reinterpret_cast<float2*>(&y[(size_t)(r0 + 8) * 64 + c]) = o;
            }
        }
    }
}

// ---------------- scatter: agg[dst] += y[src] * deg_inv[dst], 64-wide -------
__global__ void scatter_kernel(const float* __restrict__ y, const int* __restrict__ src,
                               const int* __restrict__ dst, float* __restrict__ agg) {
    size_t t = (size_t)blockIdx.x * blockDim.x + threadIdx.x;
    if (t >= (size_t)E_EDGES * 16) return;
    int e = (int)(t >> 4), q = (int)(t & 15);
    int s = src[e], d = dst[e];
    float4 v = reinterpret_cast<const float4*>(y)[(size_t)s * 16 + q];
    float di = g_deg[d];
    float* p = agg + (size_t)d * 64 + q * 4;
    asm volatile("red.global.add.v4.f32 [%0], {%1,%2,%3,%4};"
                 :: "l"(p), "f"(v.x * di), "f"(v.y * di), "f"(v.z * di), "f"(v.w * di)
                 : "memory");
}

// ---------------- per-row inverse L2 norm ----------------
__global__ void rownorm_kernel(const float* __restrict__ agg) {
    int gw = (blockIdx.x * blockDim.x + threadIdx.x) >> 5;
    int lane = threadIdx.x & 31;
    if (gw >= N_NODES) return;
    float a = agg[(size_t)gw * 64 + lane];
    float b = agg[(size_t)gw * 64 + lane + 32];
    float ss = a * a + b * b;
#pragma unroll
    for (int off = 16; off > 0; off >>= 1) ss += __shfl_xor_sync(0xffffffffu, ss, off);
    if (lane == 0) g_rn[gw] = 1.f / fmaxf(sqrtf(ss), 1e-12f);
}

// ---------------- pooling: direct global atomics ----------
__global__ void pool_kernel(const float* __restrict__ agg, const float* __restrict__ rn,
                            const int* __restrict__ batch) {
    size_t t = (size_t)blockIdx.x * blockDim.x + threadIdx.x;
    if (t >= (size_t)N_NODES * 16) return;
    int n = (int)(t >> 4), q = (int)(t & 15);
    int b = batch[n];
    float4 v = reinterpret_cast<const float4*>(agg)[(size_t)n * 16 + q];
    float r = rn[n];
    v.x *= r; v.y *= r; v.z *= r; v.w *= r;
    int base = b * 64 + q * 4;
    atomicMax(&g_gmax[base + 0], fenc(v.x));
    atomicMax(&g_gmax[base + 1], fenc(v.y));
    atomicMax(&g_gmax[base + 2], fenc(v.z));
    atomicMax(&g_gmax[base + 3], fenc(v.w));
    atomicAdd(&g_gsum[base + 0], v.x);
    atomicAdd(&g_gsum[base + 1], v.y);
    atomicAdd(&g_gsum[base + 2], v.z);
    atomicAdd(&g_gsum[base + 3], v.w);
    if (q == 0) atomicAdd(&g_cnt[b], 1.f);
}

__global__ void final_kernel(const float* __restrict__ pw, const float* __restrict__ pb,
                             float* __restrict__ out) {
    int b = threadIdx.x / 32, lane = threadIdx.x % 32;
    if (b >= NBATCH) return;
    float c = fmaxf(g_cnt[b], 1.f);
    float g0 = fdec(g_gmax[b * 64 + lane])      + g_gsum[b * 64 + lane] / c;
    float g1 = fdec(g_gmax[b * 64 + lane + 32]) + g_gsum[b * 64 + lane + 32] / c;
    float ss = g0 * g0 + g1 * g1;
#pragma unroll
    for (int off = 16; off > 0; off >>= 1) ss += __shfl_xor_sync(0xffffffffu, ss, off);
    float inv = 1.f / sqrtf(ss);
    float o = g0 * inv * pw[lane] + g1 * inv * pw[lane + 32];
#pragma unroll
    for (int off = 16; off > 0; off >>= 1) o += __shfl_xor_sync(0xffffffffu, o, off);
    if (lane == 0) out[b] = o + pb[0];
}

// ---------------- launch ----------------
extern "C" void kernel_launch(void* const* d_in, const int* in_sizes, int n_in,
                              void* d_out, int out_size) {
    const float* node_feat = (const float*)d_in[0];
    const float* cfg       = (const float*)d_in[1];
    const int*   opcode    = (const int*)d_in[2];
    const int*   eidx      = (const int*)d_in[3];
    const int*   batch     = (const int*)d_in[4];
    const float* op_emb    = (const float*)d_in[5];
    const float* type_emb  = (const float*)d_in[6];
    const float* lin_w     = (const float*)d_in[7];
    const float* lin_b     = (const float*)d_in[8];
    const float* post_w    = (const float*)d_in[9];
    const float* post_b    = (const float*)d_in[10];
    const float* wp[3] = {(const float*)d_in[11], (const float*)d_in[16], (const float*)d_in[21]};
    const float* bp[3] = {(const float*)d_in[12], (const float*)d_in[17], (const float*)d_in[22]};
    const float* wl[3] = {(const float*)d_in[13], (const float*)d_in[18], (const float*)d_in[23]};
    const float* bl[3] = {(const float*)d_in[14], (const float*)d_in[19], (const float*)d_in[24]};
    const float* wr[3] = {(const float*)d_in[15], (const float*)d_in[20], (const float*)d_in[25]};
    const int* src = eidx;
    const int* dst = eidx + E_EDGES;

    float *x_, *xp_, *aggA_, *aggB_, *y_, *rn_, *deg_;
    cudaGetSymbolAddress((void**)&x_,    g_x);
    cudaGetSymbolAddress((void**)&xp_,   g_xp);
    cudaGetSymbolAddress((void**)&aggA_, g_aggA);
    cudaGetSymbolAddress((void**)&aggB_, g_aggB);
    cudaGetSymbolAddress((void**)&y_,    g_y);
    cudaGetSymbolAddress((void**)&rn_,   g_rn);
    cudaGetSymbolAddress((void**)&deg_,  g_deg);

    const int T = 256;
    const int GEMM_GRID = (N_NODES + 63) / 64;   // BM=64
    const unsigned SCAT_GRID = (unsigned)(((size_t)E_EDGES * 16 + T - 1) / T);
    const unsigned WARP_GRID = (unsigned)(((size_t)N_NODES * 32 + T - 1) / T);
    const unsigned POOL_GRID = (unsigned)(((size_t)N_NODES * 16 + T - 1) / T);

    // launch order chosen so the ncu-captured 4th slot profiles gemm1<128>
    pad_w_kernel<<<(PK * 128 + T - 1) / T, T>>>(lin_w);                                   // 1
    gemm_initial<<<GEMM_GRID, T>>>(node_feat, cfg, opcode, op_emb, type_emb, lin_b, x_);  // 2
    zero_f<<<(N_NODES + T - 1) / T, T>>>(deg_, N_NODES);                                  // 3
    gemm1_kernel<128, false><<<GEMM_GRID, T>>>(x_, nullptr, wp[0], bp[0], wr[0], bl[0], xp_, aggA_); // 4 (captured)
    deg_kernel<<<(E_EDGES + T - 1) / T, T>>>(dst);                                        // 5
    deginv_kernel<<<(N_NODES + T - 1) / T, T>>>();                                        // 6
    pool_init_kernel<<<(NBATCH * 64 + T - 1) / T, T>>>();                                 // 7

    // layer 0 (IND=128), continued
    gemm2_kernel<128><<<GEMM_GRID, T>>>(xp_, wl[0], y_);
    scatter_kernel<<<SCAT_GRID, T>>>(y_, src, dst, aggA_);
    rownorm_kernel<<<WARP_GRID, T>>>(aggA_);

    // layer 1 (IND=64)
    gemm1_kernel<64, true><<<GEMM_GRID, T>>>(aggA_, rn_, wp[1], bp[1], wr[1], bl[1], xp_, aggB_);
    gemm2_kernel<64><<<GEMM_GRID, T>>>(xp_, wl[1], y_);
    scatter_kernel<<<SCAT_GRID, T>>>(y_, src, dst, aggB_);
    rownorm_kernel<<<WARP_GRID, T>>>(aggB_);

    // layer 2 (IND=64)
    gemm1_kernel<64, true><<<GEMM_GRID, T>>>(aggB_, rn_, wp[2], bp[2], wr[2], bl[2], xp_, aggA_);
    gemm2_kernel<64><<<GEMM_GRID, T>>>(xp_, wl[2], y_);
    scatter_kernel<<<SCAT_GRID, T>>>(y_, src, dst, aggA_);
    rownorm_kernel<<<WARP_GRID, T>>>(aggA_);

    // pooling on normalized layer-2 output
    pool_kernel<<<POOL_GRID, T>>>(aggA_, rn_, batch);
    final_kernel<<<1, 512>>>(post_w, post_b, (float*)d_out);
}